// round 11
// baseline (speedup 1.0000x reference)
#include <cuda_runtime.h>
#include <cuda_fp16.h>
#include <cstdint>
#include <math.h>

// ---------------------------------------------------------------------------
// Problem constants
// ---------------------------------------------------------------------------
#define BATCH   16384
#define FDIM    256
#define NPAIRS  2016
#define K0      2272
#define K0P     2304          // padded to multiple of 64
#define D1      2048
#define D2      2048
#define D3      1024
#define BN_EPS  1e-5f
#define NSLAB   128           // BATCH / 128 M-slabs (one stats partial each)

// ---------------------------------------------------------------------------
// Scratch (static device arrays; runtime allocation forbidden)
// ---------------------------------------------------------------------------
__device__ __half g_H0[BATCH * (size_t)K0P];    // 75.5 MB
__device__ __half g_Z0[BATCH * (size_t)D1];     // 67 MB (L0 preact -> L1 input, in place)
__device__ __half g_Z1[BATCH * (size_t)D2];     // 67 MB (L1 preact -> L2 input, in place)
__device__ __half g_Z2[BATCH * (size_t)D3];     // 33.5 MB (L2 preact, fp16; BN in GEMV head)
__device__ __half g_W0[(size_t)D1 * K0P];
__device__ __half g_W1[(size_t)D2 * D1];
__device__ __half g_W2[(size_t)D3 * D2];
__device__ float g_PS[NSLAB * D1];
__device__ float g_PQ[NSLAB * D1];
__device__ float g_SCALE[D1];
__device__ float g_SHIFT[D1];
__device__ int   g_PI[NPAIRS];
__device__ int   g_PJ[NPAIRS];

// ---------------------------------------------------------------------------
// PTX wrappers (plain sm_80+ features)
// ---------------------------------------------------------------------------
__device__ __forceinline__ uint32_t smem_u32(const void* p) {
    uint32_t a;
    asm("{ .reg .u64 t; cvta.to.shared.u64 t, %1; cvt.u32.u64 %0, t; }" : "=r"(a) : "l"(p));
    return a;
}
__device__ __forceinline__ void cp16(uint32_t saddr, const void* gaddr) {
    asm volatile("cp.async.cg.shared.global [%0], [%1], 16;" :: "r"(saddr), "l"(gaddr));
}
__device__ __forceinline__ void ldsm_x4(uint32_t* r, uint32_t addr) {
    asm volatile("ldmatrix.sync.aligned.m8n8.x4.shared.b16 {%0,%1,%2,%3}, [%4];"
        : "=r"(r[0]), "=r"(r[1]), "=r"(r[2]), "=r"(r[3]) : "r"(addr));
}
__device__ __forceinline__ void mma16816(float* d, const uint32_t* a,
                                         uint32_t b0, uint32_t b1) {
    asm volatile(
        "mma.sync.aligned.m16n8k16.row.col.f32.f16.f16.f32 "
        "{%0,%1,%2,%3}, {%4,%5,%6,%7}, {%8,%9}, {%0,%1,%2,%3};"
        : "+f"(d[0]), "+f"(d[1]), "+f"(d[2]), "+f"(d[3])
        : "r"(a[0]), "r"(a[1]), "r"(a[2]), "r"(a[3]), "r"(b0), "r"(b1));
}

// ---------------------------------------------------------------------------
// Pair table (row-major upper triangle, k=1)
// ---------------------------------------------------------------------------
__global__ void build_pairs_kernel() {
    int p = blockIdx.x * blockDim.x + threadIdx.x;
    if (p >= NPAIRS) return;
    float disc = sqrtf(16129.0f - 8.0f * (float)p);
    int i = (int)((127.0f - disc) * 0.5f);
    while (((127 * (i + 1) - (i + 1) * (i + 1)) >> 1) <= p) i++;
    while (((127 * i - i * i) >> 1) > p) i--;
    int off = (127 * i - i * i) >> 1;
    g_PI[p] = i;
    g_PJ[p] = p - off + i + 1;
}

// ---------------------------------------------------------------------------
// H0 (fp16, zero-padded to K0P) — one block per batch row
// ---------------------------------------------------------------------------
__global__ void __launch_bounds__(256) build_h0_kernel(const float* __restrict__ xv) {
    __shared__ float row[FDIM];
    int b = blockIdx.x;
    int tid = threadIdx.x;
    row[tid] = xv[(size_t)b * FDIM + tid];
    __syncthreads();
    __half* h = g_H0 + (size_t)b * K0P;
    h[tid] = __float2half_rn(row[tid]);
    const float inv255 = 1.0f / 255.0f;
    for (int p = tid; p < NPAIRS; p += 256) {
        h[FDIM + p] = __float2half_rn(row[g_PI[p]] * row[g_PJ[p]] * inv255);
    }
    if (tid < K0P - K0) h[K0 + tid] = __float2half_rn(0.0f);
}

// ---------------------------------------------------------------------------
// Weight convert/pad, 8 elems/thread: W fp32 [N, Kin] -> fp16 [N, Kout]
// ---------------------------------------------------------------------------
__global__ void __launch_bounds__(256) convert_w_kernel(
    const float* __restrict__ W, __half* __restrict__ Wh, int N, int Kin, int Kout)
{
    size_t i8 = (size_t)blockIdx.x * 256 + threadIdx.x;
    size_t total8 = (size_t)N * Kout / 8;
    if (i8 >= total8) return;
    int k = (int)((i8 * 8) % Kout);
    int n = (int)((i8 * 8) / Kout);
    __half2 o[4];
    if (k < Kin) {
        const float4* src = (const float4*)(W + (size_t)n * Kin + k);
        float4 v0 = src[0], v1 = src[1];
        o[0] = __floats2half2_rn(v0.x, v0.y);
        o[1] = __floats2half2_rn(v0.z, v0.w);
        o[2] = __floats2half2_rn(v1.x, v1.y);
        o[3] = __floats2half2_rn(v1.z, v1.w);
    } else {
        o[0] = o[1] = o[2] = o[3] = __floats2half2_rn(0.f, 0.f);
    }
    *(uint4*)(Wh + i8 * 8) = *(uint4*)o;
}

// ---------------------------------------------------------------------------
// fp16 mma.sync GEMM with fused column stats.
// CTA 128x256, BK=64, 8 warps (2M x 4N), warp tile 64x64.
// 2-stage cp.async (prefetch-then-wait_group(1): one stage always in flight),
// stage = A 16KB + B 32KB = 48KB; 2 stages = 96KB -> 2 CTAs/SM.
// M mult of 128, N mult of 256, K mult of 64.
// Per-128-row-slab column sum/sumsq -> g_PS/g_PQ[bm][bn*256 + col].
// ---------------------------------------------------------------------------
#define A_TILE_B 16384u
#define B_TILE_B 32768u
#define STAGE_B  (A_TILE_B + B_TILE_B)     // 49152
#define GEMM_SMEM (2u * STAGE_B)           // 98304

__device__ __forceinline__ void load_stage(
    uint32_t sbase, const __half* __restrict__ a, const __half* __restrict__ b,
    int kt, int K, int tid)
{
    const __half* ga = a + (size_t)kt * 64;
    #pragma unroll
    for (int i = 0; i < 4; i++) {           // A: 128 rows = 1024 chunks
        int idx = tid + i * 256;
        int row = idx >> 3;
        int ch  = idx & 7;
        uint32_t off = (uint32_t)(row << 7) + (((uint32_t)ch << 4) ^ (((uint32_t)row & 7u) << 4));
        cp16(sbase + off, ga + (size_t)row * K + (ch << 3));
    }
    const __half* gb = b + (size_t)kt * 64;
    #pragma unroll
    for (int i = 0; i < 8; i++) {           // B: 256 rows = 2048 chunks
        int idx = tid + i * 256;
        int row = idx >> 3;
        int ch  = idx & 7;
        uint32_t off = (uint32_t)(row << 7) + (((uint32_t)ch << 4) ^ (((uint32_t)row & 7u) << 4));
        cp16(sbase + A_TILE_B + off, gb + (size_t)row * K + (ch << 3));
    }
}

__global__ void __launch_bounds__(256, 2) gemm_f16_kernel(
    const __half* __restrict__ A, const __half* __restrict__ B,
    __half* __restrict__ C, int M, int N, int K)
{
    extern __shared__ char smraw[];
    const uint32_t smb = smem_u32(smraw);
    const int tid  = threadIdx.x;
    const int wid  = tid >> 5;
    const int lane = tid & 31;
    const int wm = wid & 1;            // 0..1  (M dir, 64 rows each)
    const int wn = wid >> 1;           // 0..3  (N dir, 64 cols each)
    const int bn = blockIdx.x, bm = blockIdx.y;
    const int T = K >> 6;

    const __half* a = A + (size_t)bm * 128 * K;
    const __half* b = B + (size_t)bn * 256 * K;

    float acc[4][8][4];
    #pragma unroll
    for (int x = 0; x < 4; x++)
        #pragma unroll
        for (int y = 0; y < 8; y++)
            #pragma unroll
            for (int z = 0; z < 4; z++) acc[x][y][z] = 0.0f;

    const int aRowBase = wm * 64 + (lane & 7) + ((lane >> 3) & 1) * 8;
    const uint32_t aKsel = ((lane >> 4) & 1) * 16;
    const int bRowBase = wn * 64 + ((lane >> 4) & 1) * 8 + (lane & 7);
    const uint32_t bKsel = ((lane >> 3) & 1) * 16;

    // prologue: stage 0
    load_stage(smb, a, b, 0, K, tid);
    asm volatile("cp.async.commit_group;" ::: "memory");

    for (int kt = 0; kt < T; kt++) {
        // prefetch kt+1 FIRST (other buffer is free: its last readers finished
        // before the trailing sync of iteration kt-1), then wait for kt only.
        if (kt + 1 < T) {
            load_stage(smb + (uint32_t)((kt + 1) & 1) * STAGE_B, a, b, kt + 1, K, tid);
            asm volatile("cp.async.commit_group;" ::: "memory");
            asm volatile("cp.async.wait_group 1;" ::: "memory");
        } else {
            asm volatile("cp.async.wait_group 0;" ::: "memory");
        }
        __syncthreads();

        const uint32_t sA = smb + (uint32_t)(kt & 1) * STAGE_B;
        const uint32_t sB = sA + A_TILE_B;

        #pragma unroll
        for (int kc = 0; kc < 4; kc++) {
            uint32_t fa[4][4];
            #pragma unroll
            for (int mf = 0; mf < 4; mf++) {
                int row = aRowBase + mf * 16;
                uint32_t kb = (uint32_t)kc * 32 + aKsel;
                uint32_t off = ((uint32_t)row << 7) + (kb ^ (((uint32_t)row & 7u) << 4));
                ldsm_x4(fa[mf], sA + off);
            }
            #pragma unroll
            for (int ng = 0; ng < 4; ng++) {
                uint32_t fb[4];
                int row = bRowBase + ng * 16;
                uint32_t kb = (uint32_t)kc * 32 + bKsel;
                uint32_t off = ((uint32_t)row << 7) + (kb ^ (((uint32_t)row & 7u) << 4));
                ldsm_x4(fb, sB + off);
                #pragma unroll
                for (int mf = 0; mf < 4; mf++) {
                    mma16816(acc[mf][ng * 2 + 0], fa[mf], fb[0], fb[1]);
                    mma16816(acc[mf][ng * 2 + 1], fa[mf], fb[2], fb[3]);
                }
            }
        }
        __syncthreads();   // readers done -> next iteration may overwrite other buffer
    }

    // ---- store C (fp16) ----
    const int r0 = bm * 128 + wm * 64 + (lane >> 2);
    const int c0 = bn * 256 + wn * 64 + (lane & 3) * 2;
    #pragma unroll
    for (int mf = 0; mf < 4; mf++) {
        #pragma unroll
        for (int nf = 0; nf < 8; nf++) {
            __half* p0 = C + (size_t)(r0 + mf * 16) * N + c0 + nf * 8;
            __half* p1 = C + (size_t)(r0 + mf * 16 + 8) * N + c0 + nf * 8;
            *(__half2*)p0 = __floats2half2_rn(acc[mf][nf][0], acc[mf][nf][1]);
            *(__half2*)p1 = __floats2half2_rn(acc[mf][nf][2], acc[mf][nf][3]);
        }
    }

    // ---- fused column stats over this CTA's 128 rows (fp32 accumulators) ----
    float se[8], so[8], qe[8], qo[8];
    #pragma unroll
    for (int nf = 0; nf < 8; nf++) {
        float s0 = 0.f, s1 = 0.f, q0 = 0.f, q1 = 0.f;
        #pragma unroll
        for (int mf = 0; mf < 4; mf++) {
            float a0 = acc[mf][nf][0], a1 = acc[mf][nf][1];
            float a2 = acc[mf][nf][2], a3 = acc[mf][nf][3];
            s0 += a0 + a2;  s1 += a1 + a3;
            q0 = fmaf(a0, a0, fmaf(a2, a2, q0));
            q1 = fmaf(a1, a1, fmaf(a3, a3, q1));
        }
        se[nf] = s0; so[nf] = s1; qe[nf] = q0; qo[nf] = q1;
    }
    #pragma unroll
    for (int off = 4; off <= 16; off <<= 1) {
        #pragma unroll
        for (int nf = 0; nf < 8; nf++) {
            se[nf] += __shfl_xor_sync(0xffffffffu, se[nf], off);
            so[nf] += __shfl_xor_sync(0xffffffffu, so[nf], off);
            qe[nf] += __shfl_xor_sync(0xffffffffu, qe[nf], off);
            qo[nf] += __shfl_xor_sync(0xffffffffu, qo[nf], off);
        }
    }
    // staging: ss[2][256], sq[2][256] (4KB, reuses mainloop smem)
    float* ss = (float*)smraw;
    float* sq = ss + 512;
    if ((lane >> 2) == 0) {
        #pragma unroll
        for (int nf = 0; nf < 8; nf++) {
            int col = wn * 64 + nf * 8 + (lane & 3) * 2;
            ss[wm * 256 + col]     = se[nf];
            ss[wm * 256 + col + 1] = so[nf];
            sq[wm * 256 + col]     = qe[nf];
            sq[wm * 256 + col + 1] = qo[nf];
        }
    }
    __syncthreads();
    // 256 threads cover the 256 columns
    g_PS[(size_t)bm * N + bn * 256 + tid] = ss[tid] + ss[256 + tid];
    g_PQ[(size_t)bm * N + bn * 256 + tid] = sq[tid] + sq[256 + tid];
}

// ---------------------------------------------------------------------------
// BN finalize: reduce NSLAB partials -> per-column scale/shift
// ---------------------------------------------------------------------------
__global__ void __launch_bounds__(256) bn_finalize_kernel(
    const float* __restrict__ g, const float* __restrict__ be, int D)
{
    int col = blockIdx.x * 256 + threadIdx.x;
    if (col >= D) return;
    float s = 0.0f, q = 0.0f;
    #pragma unroll 8
    for (int c = 0; c < NSLAB; c++) { s += g_PS[c * D + col]; q += g_PQ[c * D + col]; }
    float invB = 1.0f / (float)BATCH;
    float mean = s * invB;
    float var  = q * invB - mean * mean;
    float sc   = g[col] / sqrtf(var + BN_EPS);
    g_SCALE[col] = sc;
    g_SHIFT[col] = be[col] - mean * sc;
}

// BN+ReLU on half Z, in place (8 halves/thread)
__global__ void __launch_bounds__(256) bn_relu_half_inplace_kernel(
    __half* __restrict__ Z, int D, int total8)
{
    int i = blockIdx.x * 256 + threadIdx.x;
    if (i >= total8) return;
    int col = (i * 8) % D;
    __half2 v[4];
    *(uint4*)v = ((const uint4*)Z)[i];
    #pragma unroll
    for (int j = 0; j < 4; j++) {
        float2 f = __half22float2(v[j]);
        float y0 = fmaxf(0.0f, fmaf(f.x, g_SCALE[col + j * 2 + 0], g_SHIFT[col + j * 2 + 0]));
        float y1 = fmaxf(0.0f, fmaf(f.y, g_SCALE[col + j * 2 + 1], g_SHIFT[col + j * 2 + 1]));
        v[j] = __floats2half2_rn(y0, y1);
    }
    ((uint4*)Z)[i] = *(uint4*)v;
}

// ---------------------------------------------------------------------------
// Fused BN+ReLU+GEMV head over fp16 raw preacts Z2:
//   out[b] = sum_k relu(Z2[b,k]*sc[k]+sh[k]) * Wout[k] + bout
// ---------------------------------------------------------------------------
__global__ void __launch_bounds__(256) out_bn_gemv_kernel(
    const __half* __restrict__ Z2, const float* __restrict__ Wout,
    const float* __restrict__ bout, float* __restrict__ out)
{
    __shared__ float w[D3], sc[D3], sh[D3];
    int tid = threadIdx.x;
    ((float4*)w)[tid]  = ((const float4*)Wout)[tid];
    ((float4*)sc)[tid] = ((const float4*)g_SCALE)[tid];
    ((float4*)sh)[tid] = ((const float4*)g_SHIFT)[tid];
    __syncthreads();
    int warp = tid >> 5, lane = tid & 31;
    int b = blockIdx.x * 8 + warp;
    const __half* a = Z2 + (size_t)b * D3;
    float sum = 0.0f;
    #pragma unroll
    for (int it = 0; it < 4; it++) {
        int k = it * 256 + lane * 8;
        uint4 zv = *(const uint4*)(a + k);
        const __half2* h = (const __half2*)&zv;
        #pragma unroll
        for (int j = 0; j < 4; j++) {
            float2 f = __half22float2(h[j]);
            int kk = k + j * 2;
            float y0 = fmaxf(0.0f, fmaf(f.x, sc[kk + 0], sh[kk + 0]));
            float y1 = fmaxf(0.0f, fmaf(f.y, sc[kk + 1], sh[kk + 1]));
            sum = fmaf(y0, w[kk + 0], sum);
            sum = fmaf(y1, w[kk + 1], sum);
        }
    }
    #pragma unroll
    for (int off = 16; off > 0; off >>= 1) sum += __shfl_down_sync(0xFFFFFFFFu, sum, off);
    if (lane == 0) out[b] = sum + bout[0];
}

// ---------------------------------------------------------------------------
// Host launcher. Inputs: 0 xv, 1 W0, 2 b0, 3 g0, 4 be0, 5 W1, 6 b1, 7 g1,
// 8 be1, 9 W2, 10 b2, 11 g2, 12 be2, 13 Wout, 14 bout.
// b0/b1/b2 are absorbed by train-mode BatchNorm and never read.
// ---------------------------------------------------------------------------
extern "C" void kernel_launch(void* const* d_in, const int* in_sizes, int n_in,
                              void* d_out, int out_size)
{
    const float* xv   = (const float*)d_in[0];
    const float* W0   = (const float*)d_in[1];
    const float* g0   = (const float*)d_in[3];
    const float* be0  = (const float*)d_in[4];
    const float* W1   = (const float*)d_in[5];
    const float* g1   = (const float*)d_in[7];
    const float* be1  = (const float*)d_in[8];
    const float* W2   = (const float*)d_in[9];
    const float* g2   = (const float*)d_in[11];
    const float* be2  = (const float*)d_in[12];
    const float* Wout = (const float*)d_in[13];
    const float* bout = (const float*)d_in[14];
    float* out = (float*)d_out;

    cudaFuncSetAttribute(gemm_f16_kernel, cudaFuncAttributeMaxDynamicSharedMemorySize, GEMM_SMEM);

    __half *H0, *Z0, *Z1, *Z2, *W0h, *W1h, *W2h;
    cudaGetSymbolAddress((void**)&H0,  g_H0);
    cudaGetSymbolAddress((void**)&Z0,  g_Z0);
    cudaGetSymbolAddress((void**)&Z1,  g_Z1);
    cudaGetSymbolAddress((void**)&Z2,  g_Z2);
    cudaGetSymbolAddress((void**)&W0h, g_W0);
    cudaGetSymbolAddress((void**)&W1h, g_W1);
    cudaGetSymbolAddress((void**)&W2h, g_W2);

    // frontend + weight prep
    build_pairs_kernel<<<8, 256>>>();
    build_h0_kernel<<<BATCH, 256>>>(xv);
    convert_w_kernel<<<(int)(((size_t)D1 * K0P / 8 + 255) / 256), 256>>>(W0, W0h, D1, K0, K0P);
    convert_w_kernel<<<(int)(((size_t)D2 * D1 / 8 + 255) / 256), 256>>>(W1, W1h, D2, D1, D1);
    convert_w_kernel<<<(int)(((size_t)D3 * D2 / 8 + 255) / 256), 256>>>(W2, W2h, D3, D2, D2);

    // layer 0: Z0 = H0 @ W0^T (stats fused) -> BN+ReLU in place
    gemm_f16_kernel<<<dim3(D1 / 256, BATCH / 128), 256, GEMM_SMEM>>>(H0, W0h, Z0, BATCH, D1, K0P);
    bn_finalize_kernel<<<D1 / 256, 256>>>(g0, be0, D1);
    bn_relu_half_inplace_kernel<<<(BATCH * D1 / 8) / 256, 256>>>(Z0, D1, BATCH * D1 / 8);

    // layer 1: Z1 = Z0 @ W1^T (stats fused) -> BN+ReLU in place
    gemm_f16_kernel<<<dim3(D2 / 256, BATCH / 128), 256, GEMM_SMEM>>>(Z0, W1h, Z1, BATCH, D2, D1);
    bn_finalize_kernel<<<D2 / 256, 256>>>(g1, be1, D2);
    bn_relu_half_inplace_kernel<<<(BATCH * D2 / 8) / 256, 256>>>(Z1, D2, BATCH * D2 / 8);

    // layer 2: Z2 = Z1 @ W2^T (stats fused; fp16 raw preacts)
    gemm_f16_kernel<<<dim3(D3 / 256, BATCH / 128), 256, GEMM_SMEM>>>(Z1, W2h, Z2, BATCH, D3, D2);
    bn_finalize_kernel<<<D3 / 256, 256>>>(g2, be2, D3);

    // fused BN2+ReLU+GEMV head
    out_bn_gemv_kernel<<<BATCH / 8, 256>>>(Z2, Wout, bout, out);
}

// round 12
// speedup vs baseline: 3.1122x; 3.1122x over previous
#include <cuda_runtime.h>
#include <cuda_fp16.h>
#include <cstdint>
#include <math.h>

// ---------------------------------------------------------------------------
// Problem constants
// ---------------------------------------------------------------------------
#define BATCH   16384
#define FDIM    256
#define NPAIRS  2016
#define K0      2272
#define K0P     2304          // padded to multiple of 64
#define D1      2048
#define D2      2048
#define D3      1024
#define BN_EPS  1e-5f
#define NSLAB   128           // BATCH / 128 M-slabs (one stats partial each)

// ---------------------------------------------------------------------------
// Scratch (static device arrays; runtime allocation forbidden)
// ---------------------------------------------------------------------------
__device__ __half g_H0[BATCH * (size_t)K0P];          // 75.5 MB
__device__ __half g_A [BATCH * (size_t)D1];           // 67 MB (activations, reused L1/L2 inputs)
__device__ float  g_Z [BATCH * (size_t)D1];           // 134 MB (L0/L1 preacts, fp32, reused)
__device__ __half g_Z2[BATCH * (size_t)D3];           // 33.5 MB (L2 preacts, fp16)
__device__ __half g_W0[(size_t)D1 * K0P];
__device__ __half g_W1[(size_t)D2 * D1];
__device__ __half g_W2[(size_t)D3 * D2];
__device__ float g_PS[NSLAB * D1];
__device__ float g_PQ[NSLAB * D1];
__device__ float g_SCALE[D1];
__device__ float g_SHIFT[D1];
__device__ int   g_PI[NPAIRS];
__device__ int   g_PJ[NPAIRS];

// ---------------------------------------------------------------------------
// PTX wrappers (plain sm_80+ features)
// ---------------------------------------------------------------------------
__device__ __forceinline__ uint32_t smem_u32(const void* p) {
    uint32_t a;
    asm("{ .reg .u64 t; cvta.to.shared.u64 t, %1; cvt.u32.u64 %0, t; }" : "=r"(a) : "l"(p));
    return a;
}
__device__ __forceinline__ void cp16(uint32_t saddr, const void* gaddr) {
    asm volatile("cp.async.cg.shared.global [%0], [%1], 16;" :: "r"(saddr), "l"(gaddr));
}
__device__ __forceinline__ void ldsm_x4(uint32_t* r, uint32_t addr) {
    asm volatile("ldmatrix.sync.aligned.m8n8.x4.shared.b16 {%0,%1,%2,%3}, [%4];"
        : "=r"(r[0]), "=r"(r[1]), "=r"(r[2]), "=r"(r[3]) : "r"(addr));
}
__device__ __forceinline__ void mma16816(float* d, const uint32_t* a,
                                         uint32_t b0, uint32_t b1) {
    asm volatile(
        "mma.sync.aligned.m16n8k16.row.col.f32.f16.f16.f32 "
        "{%0,%1,%2,%3}, {%4,%5,%6,%7}, {%8,%9}, {%0,%1,%2,%3};"
        : "+f"(d[0]), "+f"(d[1]), "+f"(d[2]), "+f"(d[3])
        : "r"(a[0]), "r"(a[1]), "r"(a[2]), "r"(a[3]), "r"(b0), "r"(b1));
}

// ---------------------------------------------------------------------------
// Pair table (row-major upper triangle, k=1)
// ---------------------------------------------------------------------------
__global__ void build_pairs_kernel() {
    int p = blockIdx.x * blockDim.x + threadIdx.x;
    if (p >= NPAIRS) return;
    float disc = sqrtf(16129.0f - 8.0f * (float)p);
    int i = (int)((127.0f - disc) * 0.5f);
    while (((127 * (i + 1) - (i + 1) * (i + 1)) >> 1) <= p) i++;
    while (((127 * i - i * i) >> 1) > p) i--;
    int off = (127 * i - i * i) >> 1;
    g_PI[p] = i;
    g_PJ[p] = p - off + i + 1;
}

// ---------------------------------------------------------------------------
// H0 (fp16, zero-padded to K0P) — one block per batch row
// ---------------------------------------------------------------------------
__global__ void __launch_bounds__(256) build_h0_kernel(const float* __restrict__ xv) {
    __shared__ float row[FDIM];
    int b = blockIdx.x;
    int tid = threadIdx.x;
    row[tid] = xv[(size_t)b * FDIM + tid];
    __syncthreads();
    __half* h = g_H0 + (size_t)b * K0P;
    h[tid] = __float2half_rn(row[tid]);
    const float inv255 = 1.0f / 255.0f;
    for (int p = tid; p < NPAIRS; p += 256) {
        h[FDIM + p] = __float2half_rn(row[g_PI[p]] * row[g_PJ[p]] * inv255);
    }
    if (tid < K0P - K0) h[K0 + tid] = __float2half_rn(0.0f);
}

// ---------------------------------------------------------------------------
// Weight convert/pad, 8 elems/thread: W fp32 [N, Kin] -> fp16 [N, Kout]
// ---------------------------------------------------------------------------
__global__ void __launch_bounds__(256) convert_w_kernel(
    const float* __restrict__ W, __half* __restrict__ Wh, int N, int Kin, int Kout)
{
    size_t i8 = (size_t)blockIdx.x * 256 + threadIdx.x;
    size_t total8 = (size_t)N * Kout / 8;
    if (i8 >= total8) return;
    int k = (int)((i8 * 8) % Kout);
    int n = (int)((i8 * 8) / Kout);
    __half2 o[4];
    if (k < Kin) {
        const float4* src = (const float4*)(W + (size_t)n * Kin + k);
        float4 v0 = src[0], v1 = src[1];
        o[0] = __floats2half2_rn(v0.x, v0.y);
        o[1] = __floats2half2_rn(v0.z, v0.w);
        o[2] = __floats2half2_rn(v1.x, v1.y);
        o[3] = __floats2half2_rn(v1.z, v1.w);
    } else {
        o[0] = o[1] = o[2] = o[3] = __floats2half2_rn(0.f, 0.f);
    }
    *(uint4*)(Wh + i8 * 8) = *(uint4*)o;
}

// ---------------------------------------------------------------------------
// fp16 mma.sync GEMM (templated output dtype) with fused column stats.
// ROUND-6 CHAMPION CONFIG: CTA 128x128, BK=64, 4 warps (2M x 2N),
// warp tile 64x64, 3-stage cp.async (wait_group 1), 96KB smem -> 2 CTAs/SM.
// Per-128-row-slab column sum/sumsq -> g_PS/g_PQ (deterministic).
// ---------------------------------------------------------------------------
#define A_TILE_B 16384u
#define B_TILE_B 16384u
#define STAGE_B  (A_TILE_B + B_TILE_B)     // 32768
#define GEMM_SMEM (3u * STAGE_B)           // 98304

__device__ __forceinline__ void load_stage(
    uint32_t sbase, const __half* __restrict__ a, const __half* __restrict__ b,
    int kt, int K, int tid)
{
    const __half* ga = a + (size_t)kt * 64;
    #pragma unroll
    for (int i = 0; i < 8; i++) {
        int idx = tid + i * 128;            // 0..1023
        int row = idx >> 3;                 // 0..127
        int ch  = idx & 7;
        uint32_t off = (uint32_t)(row << 7) + (((uint32_t)ch << 4) ^ (((uint32_t)row & 7u) << 4));
        cp16(sbase + off, ga + (size_t)row * K + (ch << 3));
    }
    const __half* gb = b + (size_t)kt * 64;
    #pragma unroll
    for (int i = 0; i < 8; i++) {
        int idx = tid + i * 128;
        int row = idx >> 3;
        int ch  = idx & 7;
        uint32_t off = (uint32_t)(row << 7) + (((uint32_t)ch << 4) ^ (((uint32_t)row & 7u) << 4));
        cp16(sbase + A_TILE_B + off, gb + (size_t)row * K + (ch << 3));
    }
}

template <typename OutT>
__device__ __forceinline__ void store_pair(OutT* p, float a0, float a1);
template <>
__device__ __forceinline__ void store_pair<float>(float* p, float a0, float a1) {
    *(float2*)p = make_float2(a0, a1);
}
template <>
__device__ __forceinline__ void store_pair<__half>(__half* p, float a0, float a1) {
    *(__half2*)p = __floats2half2_rn(a0, a1);
}

template <typename OutT>
__global__ void __launch_bounds__(128, 2) gemm_f16_kernel(
    const __half* __restrict__ A, const __half* __restrict__ B,
    OutT* __restrict__ C, int M, int N, int K)
{
    extern __shared__ char smraw[];
    const uint32_t smb = smem_u32(smraw);
    const int tid  = threadIdx.x;
    const int wid  = tid >> 5;
    const int lane = tid & 31;
    const int wm = wid & 1;            // 0..1  (M dir, 64 rows each)
    const int wn = wid >> 1;           // 0..1  (N dir, 64 cols each)
    const int bn = blockIdx.x, bm = blockIdx.y;
    const int T = K >> 6;

    const __half* a = A + (size_t)bm * 128 * K;
    const __half* b = B + (size_t)bn * 128 * K;

    float acc[4][8][4];
    #pragma unroll
    for (int x = 0; x < 4; x++)
        #pragma unroll
        for (int y = 0; y < 8; y++)
            #pragma unroll
            for (int z = 0; z < 4; z++) acc[x][y][z] = 0.0f;

    const int aRowBase = wm * 64 + (lane & 7) + ((lane >> 3) & 1) * 8;
    const uint32_t aKsel = ((lane >> 4) & 1) * 16;
    const int bRowBase = wn * 64 + ((lane >> 4) & 1) * 8 + (lane & 7);
    const uint32_t bKsel = ((lane >> 3) & 1) * 16;

    // prologue: stages 0,1
    #pragma unroll
    for (int s = 0; s < 2; s++) {
        load_stage(smb + (uint32_t)s * STAGE_B, a, b, s, K, tid);
        asm volatile("cp.async.commit_group;" ::: "memory");
    }

    int buf = 0;
    for (int kt = 0; kt < T; kt++) {
        if (kt + 1 < T) asm volatile("cp.async.wait_group 1;" ::: "memory");
        else            asm volatile("cp.async.wait_group 0;" ::: "memory");
        __syncthreads();

        if (kt + 2 < T) {
            int nb = kt + 2 - 3 * ((kt + 2) / 3);
            load_stage(smb + (uint32_t)nb * STAGE_B, a, b, kt + 2, K, tid);
            asm volatile("cp.async.commit_group;" ::: "memory");
        }

        const uint32_t sA = smb + (uint32_t)buf * STAGE_B;
        const uint32_t sB = sA + A_TILE_B;

        #pragma unroll
        for (int kc = 0; kc < 4; kc++) {
            uint32_t fa[4][4];
            #pragma unroll
            for (int mf = 0; mf < 4; mf++) {
                int row = aRowBase + mf * 16;
                uint32_t kb = (uint32_t)kc * 32 + aKsel;
                uint32_t off = ((uint32_t)row << 7) + (kb ^ (((uint32_t)row & 7u) << 4));
                ldsm_x4(fa[mf], sA + off);
            }
            #pragma unroll
            for (int ng = 0; ng < 4; ng++) {
                uint32_t fb[4];
                int row = bRowBase + ng * 16;
                uint32_t kb = (uint32_t)kc * 32 + bKsel;
                uint32_t off = ((uint32_t)row << 7) + (kb ^ (((uint32_t)row & 7u) << 4));
                ldsm_x4(fb, sB + off);
                #pragma unroll
                for (int mf = 0; mf < 4; mf++) {
                    mma16816(acc[mf][ng * 2 + 0], fa[mf], fb[0], fb[1]);
                    mma16816(acc[mf][ng * 2 + 1], fa[mf], fb[2], fb[3]);
                }
            }
        }
        buf++;
        if (buf == 3) buf = 0;
        __syncthreads();
    }

    // ---- store C ----
    const int r0 = bm * 128 + wm * 64 + (lane >> 2);
    const int c0 = bn * 128 + wn * 64 + (lane & 3) * 2;
    #pragma unroll
    for (int mf = 0; mf < 4; mf++) {
        #pragma unroll
        for (int nf = 0; nf < 8; nf++) {
            OutT* p0 = C + (size_t)(r0 + mf * 16) * N + c0 + nf * 8;
            OutT* p1 = C + (size_t)(r0 + mf * 16 + 8) * N + c0 + nf * 8;
            store_pair<OutT>(p0, acc[mf][nf][0], acc[mf][nf][1]);
            store_pair<OutT>(p1, acc[mf][nf][2], acc[mf][nf][3]);
        }
    }

    // ---- fused column stats over this CTA's 128 rows (fp32 accumulators) ----
    float se[8], so[8], qe[8], qo[8];
    #pragma unroll
    for (int nf = 0; nf < 8; nf++) {
        float s0 = 0.f, s1 = 0.f, q0 = 0.f, q1 = 0.f;
        #pragma unroll
        for (int mf = 0; mf < 4; mf++) {
            float a0 = acc[mf][nf][0], a1 = acc[mf][nf][1];
            float a2 = acc[mf][nf][2], a3 = acc[mf][nf][3];
            s0 += a0 + a2;  s1 += a1 + a3;
            q0 = fmaf(a0, a0, fmaf(a2, a2, q0));
            q1 = fmaf(a1, a1, fmaf(a3, a3, q1));
        }
        se[nf] = s0; so[nf] = s1; qe[nf] = q0; qo[nf] = q1;
    }
    #pragma unroll
    for (int off = 4; off <= 16; off <<= 1) {
        #pragma unroll
        for (int nf = 0; nf < 8; nf++) {
            se[nf] += __shfl_xor_sync(0xffffffffu, se[nf], off);
            so[nf] += __shfl_xor_sync(0xffffffffu, so[nf], off);
            qe[nf] += __shfl_xor_sync(0xffffffffu, qe[nf], off);
            qo[nf] += __shfl_xor_sync(0xffffffffu, qo[nf], off);
        }
    }
    float* ss = (float*)smraw;           // [2][128]
    float* sq = ss + 256;                // [2][128]
    if ((lane >> 2) == 0) {
        #pragma unroll
        for (int nf = 0; nf < 8; nf++) {
            int col = wn * 64 + nf * 8 + (lane & 3) * 2;
            ss[wm * 128 + col]     = se[nf];
            ss[wm * 128 + col + 1] = so[nf];
            sq[wm * 128 + col]     = qe[nf];
            sq[wm * 128 + col + 1] = qo[nf];
        }
    }
    __syncthreads();
    if (tid < 128) {
        g_PS[(size_t)bm * N + bn * 128 + tid] = ss[tid] + ss[128 + tid];
        g_PQ[(size_t)bm * N + bn * 128 + tid] = sq[tid] + sq[128 + tid];
    }
}

// ---------------------------------------------------------------------------
// BN finalize: reduce NSLAB partials -> per-column scale/shift
// ---------------------------------------------------------------------------
__global__ void __launch_bounds__(256) bn_finalize_kernel(
    const float* __restrict__ g, const float* __restrict__ be, int D)
{
    int col = blockIdx.x * 256 + threadIdx.x;
    if (col >= D) return;
    float s = 0.0f, q = 0.0f;
    #pragma unroll 8
    for (int c = 0; c < NSLAB; c++) { s += g_PS[c * D + col]; q += g_PQ[c * D + col]; }
    float invB = 1.0f / (float)BATCH;
    float mean = s * invB;
    float var  = q * invB - mean * mean;
    float sc   = g[col] / sqrtf(var + BN_EPS);
    g_SCALE[col] = sc;
    g_SHIFT[col] = be[col] - mean * sc;
}

// BN+ReLU: fp32 Z -> fp16 activations (round-6 proven path)
__global__ void __launch_bounds__(256) bn_relu_half_kernel(
    const float* __restrict__ Z, __half* __restrict__ Ao, int D, int total4)
{
    int i = blockIdx.x * 256 + threadIdx.x;
    if (i >= total4) return;
    int col = (i * 4) % D;
    float4 v = ((const float4*)Z)[i];
    float y0 = fmaxf(0.0f, fmaf(v.x, g_SCALE[col + 0], g_SHIFT[col + 0]));
    float y1 = fmaxf(0.0f, fmaf(v.y, g_SCALE[col + 1], g_SHIFT[col + 1]));
    float y2 = fmaxf(0.0f, fmaf(v.z, g_SCALE[col + 2], g_SHIFT[col + 2]));
    float y3 = fmaxf(0.0f, fmaf(v.w, g_SCALE[col + 3], g_SHIFT[col + 3]));
    ((__half2*)Ao)[i * 2 + 0] = __floats2half2_rn(y0, y1);
    ((__half2*)Ao)[i * 2 + 1] = __floats2half2_rn(y2, y3);
}

// ---------------------------------------------------------------------------
// Fused BN+ReLU+GEMV head over fp16 raw preacts Z2:
//   out[b] = sum_k relu(Z2[b,k]*sc[k]+sh[k]) * Wout[k] + bout
// ---------------------------------------------------------------------------
__global__ void __launch_bounds__(256) out_bn_gemv_kernel(
    const __half* __restrict__ Z2, const float* __restrict__ Wout,
    const float* __restrict__ bout, float* __restrict__ out)
{
    __shared__ float w[D3], sc[D3], sh[D3];
    int tid = threadIdx.x;
    ((float4*)w)[tid]  = ((const float4*)Wout)[tid];
    ((float4*)sc)[tid] = ((const float4*)g_SCALE)[tid];
    ((float4*)sh)[tid] = ((const float4*)g_SHIFT)[tid];
    __syncthreads();
    int warp = tid >> 5, lane = tid & 31;
    int b = blockIdx.x * 8 + warp;
    const __half* a = Z2 + (size_t)b * D3;
    float sum = 0.0f;
    #pragma unroll
    for (int it = 0; it < 4; it++) {
        int k = it * 256 + lane * 8;
        uint4 zv = *(const uint4*)(a + k);
        const __half2* h = (const __half2*)&zv;
        #pragma unroll
        for (int j = 0; j < 4; j++) {
            float2 f = __half22float2(h[j]);
            int kk = k + j * 2;
            float y0 = fmaxf(0.0f, fmaf(f.x, sc[kk + 0], sh[kk + 0]));
            float y1 = fmaxf(0.0f, fmaf(f.y, sc[kk + 1], sh[kk + 1]));
            sum = fmaf(y0, w[kk + 0], sum);
            sum = fmaf(y1, w[kk + 1], sum);
        }
    }
    #pragma unroll
    for (int off = 16; off > 0; off >>= 1) sum += __shfl_down_sync(0xFFFFFFFFu, sum, off);
    if (lane == 0) out[b] = sum + bout[0];
}

// ---------------------------------------------------------------------------
// Host launcher. Inputs: 0 xv, 1 W0, 2 b0, 3 g0, 4 be0, 5 W1, 6 b1, 7 g1,
// 8 be1, 9 W2, 10 b2, 11 g2, 12 be2, 13 Wout, 14 bout.
// b0/b1/b2 are absorbed by train-mode BatchNorm and never read.
// ---------------------------------------------------------------------------
extern "C" void kernel_launch(void* const* d_in, const int* in_sizes, int n_in,
                              void* d_out, int out_size)
{
    const float* xv   = (const float*)d_in[0];
    const float* W0   = (const float*)d_in[1];
    const float* g0   = (const float*)d_in[3];
    const float* be0  = (const float*)d_in[4];
    const float* W1   = (const float*)d_in[5];
    const float* g1   = (const float*)d_in[7];
    const float* be1  = (const float*)d_in[8];
    const float* W2   = (const float*)d_in[9];
    const float* g2   = (const float*)d_in[11];
    const float* be2  = (const float*)d_in[12];
    const float* Wout = (const float*)d_in[13];
    const float* bout = (const float*)d_in[14];
    float* out = (float*)d_out;

    cudaFuncSetAttribute(gemm_f16_kernel<float>,  cudaFuncAttributeMaxDynamicSharedMemorySize, GEMM_SMEM);
    cudaFuncSetAttribute(gemm_f16_kernel<__half>, cudaFuncAttributeMaxDynamicSharedMemorySize, GEMM_SMEM);

    __half *H0, *Ap, *Z2, *W0h, *W1h, *W2h;
    float *Z;
    cudaGetSymbolAddress((void**)&H0,  g_H0);
    cudaGetSymbolAddress((void**)&Ap,  g_A);
    cudaGetSymbolAddress((void**)&Z,   g_Z);
    cudaGetSymbolAddress((void**)&Z2,  g_Z2);
    cudaGetSymbolAddress((void**)&W0h, g_W0);
    cudaGetSymbolAddress((void**)&W1h, g_W1);
    cudaGetSymbolAddress((void**)&W2h, g_W2);

    // frontend + weight prep
    build_pairs_kernel<<<8, 256>>>();
    build_h0_kernel<<<BATCH, 256>>>(xv);
    convert_w_kernel<<<(int)(((size_t)D1 * K0P / 8 + 255) / 256), 256>>>(W0, W0h, D1, K0, K0P);
    convert_w_kernel<<<(int)(((size_t)D2 * D1 / 8 + 255) / 256), 256>>>(W1, W1h, D2, D1, D1);
    convert_w_kernel<<<(int)(((size_t)D3 * D2 / 8 + 255) / 256), 256>>>(W2, W2h, D3, D2, D2);

    // layer 0: Z = H0 @ W0^T (fp32, stats fused) -> BN+ReLU -> fp16 A
    gemm_f16_kernel<float><<<dim3(D1 / 128, BATCH / 128), 128, GEMM_SMEM>>>(H0, W0h, Z, BATCH, D1, K0P);
    bn_finalize_kernel<<<D1 / 256, 256>>>(g0, be0, D1);
    bn_relu_half_kernel<<<(BATCH * D1 / 4) / 256, 256>>>(Z, Ap, D1, BATCH * D1 / 4);

    // layer 1: Z = A @ W1^T (fp32, stats fused) -> BN+ReLU -> fp16 A
    gemm_f16_kernel<float><<<dim3(D2 / 128, BATCH / 128), 128, GEMM_SMEM>>>(Ap, W1h, Z, BATCH, D2, D1);
    bn_finalize_kernel<<<D2 / 256, 256>>>(g1, be1, D2);
    bn_relu_half_kernel<<<(BATCH * D2 / 4) / 256, 256>>>(Z, Ap, D2, BATCH * D2 / 4);

    // layer 2: Z2 = A @ W2^T (fp16 out, stats fused) — BN folded into the head
    gemm_f16_kernel<__half><<<dim3(D3 / 128, BATCH / 128), 128, GEMM_SMEM>>>(Ap, W2h, Z2, BATCH, D3, D2);
    bn_finalize_kernel<<<D3 / 256, 256>>>(g2, be2, D3);

    // fused BN2+ReLU+GEMV head
    out_bn_gemv_kernel<<<BATCH / 8, 256>>>(Z2, Wout, bout, out);
}

// round 13
// speedup vs baseline: 3.1989x; 1.0278x over previous
#include <cuda_runtime.h>
#include <cuda_fp16.h>
#include <cstdint>
#include <math.h>

// ---------------------------------------------------------------------------
// Problem constants
// ---------------------------------------------------------------------------
#define BATCH   16384
#define FDIM    256
#define NPAIRS  2016
#define K0      2272
#define K0P     2304          // padded to multiple of 64
#define D1      2048
#define D2      2048
#define D3      1024
#define BN_EPS  1e-5f
#define NSLAB   128           // BATCH / 128 M-slabs (one stats partial each)

// ---------------------------------------------------------------------------
// Scratch (static device arrays; runtime allocation forbidden)
// ---------------------------------------------------------------------------
__device__ __half g_H0[BATCH * (size_t)K0P];          // 75.5 MB
__device__ __half g_A [BATCH * (size_t)D1];           // 67 MB (activations, reused L1/L2 inputs)
__device__ float  g_Z [BATCH * (size_t)D1];           // 134 MB (L0/L1 preacts, fp32, reused)
__device__ __half g_Z2[BATCH * (size_t)D3];           // 33.5 MB (L2 preacts, fp16)
__device__ __half g_W0[(size_t)D1 * K0P];
__device__ __half g_W1[(size_t)D2 * D1];
__device__ __half g_W2[(size_t)D3 * D2];
__device__ float g_PS[NSLAB * D1];
__device__ float g_PQ[NSLAB * D1];
__device__ float g_SCALE[D1];
__device__ float g_SHIFT[D1];
__device__ uchar2 g_PIJ[NPAIRS];                      // packed (i, j) per pair

// ---------------------------------------------------------------------------
// PTX wrappers (plain sm_80+ features)
// ---------------------------------------------------------------------------
__device__ __forceinline__ uint32_t smem_u32(const void* p) {
    uint32_t a;
    asm("{ .reg .u64 t; cvta.to.shared.u64 t, %1; cvt.u32.u64 %0, t; }" : "=r"(a) : "l"(p));
    return a;
}
__device__ __forceinline__ void cp16(uint32_t saddr, const void* gaddr) {
    asm volatile("cp.async.cg.shared.global [%0], [%1], 16;" :: "r"(saddr), "l"(gaddr));
}
__device__ __forceinline__ void ldsm_x4(uint32_t* r, uint32_t addr) {
    asm volatile("ldmatrix.sync.aligned.m8n8.x4.shared.b16 {%0,%1,%2,%3}, [%4];"
        : "=r"(r[0]), "=r"(r[1]), "=r"(r[2]), "=r"(r[3]) : "r"(addr));
}
__device__ __forceinline__ void mma16816(float* d, const uint32_t* a,
                                         uint32_t b0, uint32_t b1) {
    asm volatile(
        "mma.sync.aligned.m16n8k16.row.col.f32.f16.f16.f32 "
        "{%0,%1,%2,%3}, {%4,%5,%6,%7}, {%8,%9}, {%0,%1,%2,%3};"
        : "+f"(d[0]), "+f"(d[1]), "+f"(d[2]), "+f"(d[3])
        : "r"(a[0]), "r"(a[1]), "r"(a[2]), "r"(a[3]), "r"(b0), "r"(b1));
}

// ---------------------------------------------------------------------------
// Pair table (row-major upper triangle, k=1), packed uchar2
// ---------------------------------------------------------------------------
__global__ void build_pairs_kernel() {
    int p = blockIdx.x * blockDim.x + threadIdx.x;
    if (p >= NPAIRS) return;
    float disc = sqrtf(16129.0f - 8.0f * (float)p);
    int i = (int)((127.0f - disc) * 0.5f);
    while (((127 * (i + 1) - (i + 1) * (i + 1)) >> 1) <= p) i++;
    while (((127 * i - i * i) >> 1) > p) i--;
    int off = (127 * i - i * i) >> 1;
    int j = p - off + i + 1;
    g_PIJ[p] = make_uchar2((unsigned char)i, (unsigned char)j);
}

// ---------------------------------------------------------------------------
// H0 (fp16, zero-padded to K0P) — one block per batch row, vectorized:
// thread t < 252 computes pairs 8t..8t+7 (one uint4 table load, one uint4 store)
// ---------------------------------------------------------------------------
__global__ void __launch_bounds__(256) build_h0_kernel(const float* __restrict__ xv) {
    __shared__ float row[FDIM];
    int b = blockIdx.x;
    int tid = threadIdx.x;
    row[tid] = xv[(size_t)b * FDIM + tid];
    __syncthreads();
    __half* h = g_H0 + (size_t)b * K0P;
    h[tid] = __float2half_rn(row[tid]);                 // linear features (coalesced 2B/warp-contig)
    const float inv255 = 1.0f / 255.0f;
    if (tid < NPAIRS / 8) {                             // 252 threads, 8 pairs each
        uint4 tbl = *(const uint4*)(g_PIJ + tid * 8);   // 8 uchar2 pairs
        const unsigned char* ij = (const unsigned char*)&tbl;
        __half2 o[4];
        #pragma unroll
        for (int q = 0; q < 4; q++) {
            float v0 = row[ij[q * 4 + 0]] * row[ij[q * 4 + 1]] * inv255;
            float v1 = row[ij[q * 4 + 2]] * row[ij[q * 4 + 3]] * inv255;
            o[q] = __floats2half2_rn(v0, v1);
        }
        *(uint4*)(h + FDIM + tid * 8) = *(uint4*)o;
    } else if (tid < NPAIRS / 8 + 4) {                  // zero pad 2272..2303 (32 halves)
        int q = tid - NPAIRS / 8;
        *(uint2*)(h + K0 + q * 8) = make_uint2(0u, 0u);
    }
}

// ---------------------------------------------------------------------------
// Weight convert/pad, 8 elems/thread: W fp32 [N, Kin] -> fp16 [N, Kout]
// ---------------------------------------------------------------------------
__global__ void __launch_bounds__(256) convert_w_kernel(
    const float* __restrict__ W, __half* __restrict__ Wh, int N, int Kin, int Kout)
{
    size_t i8 = (size_t)blockIdx.x * 256 + threadIdx.x;
    size_t total8 = (size_t)N * Kout / 8;
    if (i8 >= total8) return;
    int k = (int)((i8 * 8) % Kout);
    int n = (int)((i8 * 8) / Kout);
    __half2 o[4];
    if (k < Kin) {
        const float4* src = (const float4*)(W + (size_t)n * Kin + k);
        float4 v0 = src[0], v1 = src[1];
        o[0] = __floats2half2_rn(v0.x, v0.y);
        o[1] = __floats2half2_rn(v0.z, v0.w);
        o[2] = __floats2half2_rn(v1.x, v1.y);
        o[3] = __floats2half2_rn(v1.z, v1.w);
    } else {
        o[0] = o[1] = o[2] = o[3] = __floats2half2_rn(0.f, 0.f);
    }
    *(uint4*)(Wh + i8 * 8) = *(uint4*)o;
}

// ---------------------------------------------------------------------------
// fp16 mma.sync GEMM (templated output dtype) with fused column stats.
// CHAMPION CONFIG (round 6/12): CTA 128x128, BK=64, 4 warps (2M x 2N),
// warp tile 64x64, 3-stage cp.async (wait_group 1), 96KB smem -> 2 CTAs/SM.
// ---------------------------------------------------------------------------
#define A_TILE_B 16384u
#define B_TILE_B 16384u
#define STAGE_B  (A_TILE_B + B_TILE_B)     // 32768
#define GEMM_SMEM (3u * STAGE_B)           // 98304

__device__ __forceinline__ void load_stage(
    uint32_t sbase, const __half* __restrict__ a, const __half* __restrict__ b,
    int kt, int K, int tid)
{
    const __half* ga = a + (size_t)kt * 64;
    #pragma unroll
    for (int i = 0; i < 8; i++) {
        int idx = tid + i * 128;            // 0..1023
        int row = idx >> 3;                 // 0..127
        int ch  = idx & 7;
        uint32_t off = (uint32_t)(row << 7) + (((uint32_t)ch << 4) ^ (((uint32_t)row & 7u) << 4));
        cp16(sbase + off, ga + (size_t)row * K + (ch << 3));
    }
    const __half* gb = b + (size_t)kt * 64;
    #pragma unroll
    for (int i = 0; i < 8; i++) {
        int idx = tid + i * 128;
        int row = idx >> 3;
        int ch  = idx & 7;
        uint32_t off = (uint32_t)(row << 7) + (((uint32_t)ch << 4) ^ (((uint32_t)row & 7u) << 4));
        cp16(sbase + A_TILE_B + off, gb + (size_t)row * K + (ch << 3));
    }
}

template <typename OutT>
__device__ __forceinline__ void store_pair(OutT* p, float a0, float a1);
template <>
__device__ __forceinline__ void store_pair<float>(float* p, float a0, float a1) {
    *(float2*)p = make_float2(a0, a1);
}
template <>
__device__ __forceinline__ void store_pair<__half>(__half* p, float a0, float a1) {
    *(__half2*)p = __floats2half2_rn(a0, a1);
}

template <typename OutT>
__global__ void __launch_bounds__(128, 2) gemm_f16_kernel(
    const __half* __restrict__ A, const __half* __restrict__ B,
    OutT* __restrict__ C, int M, int N, int K)
{
    extern __shared__ char smraw[];
    const uint32_t smb = smem_u32(smraw);
    const int tid  = threadIdx.x;
    const int wid  = tid >> 5;
    const int lane = tid & 31;
    const int wm = wid & 1;
    const int wn = wid >> 1;
    const int bn = blockIdx.x, bm = blockIdx.y;
    const int T = K >> 6;

    const __half* a = A + (size_t)bm * 128 * K;
    const __half* b = B + (size_t)bn * 128 * K;

    float acc[4][8][4];
    #pragma unroll
    for (int x = 0; x < 4; x++)
        #pragma unroll
        for (int y = 0; y < 8; y++)
            #pragma unroll
            for (int z = 0; z < 4; z++) acc[x][y][z] = 0.0f;

    const int aRowBase = wm * 64 + (lane & 7) + ((lane >> 3) & 1) * 8;
    const uint32_t aKsel = ((lane >> 4) & 1) * 16;
    const int bRowBase = wn * 64 + ((lane >> 4) & 1) * 8 + (lane & 7);
    const uint32_t bKsel = ((lane >> 3) & 1) * 16;

    #pragma unroll
    for (int s = 0; s < 2; s++) {
        load_stage(smb + (uint32_t)s * STAGE_B, a, b, s, K, tid);
        asm volatile("cp.async.commit_group;" ::: "memory");
    }

    int buf = 0;
    for (int kt = 0; kt < T; kt++) {
        if (kt + 1 < T) asm volatile("cp.async.wait_group 1;" ::: "memory");
        else            asm volatile("cp.async.wait_group 0;" ::: "memory");
        __syncthreads();

        if (kt + 2 < T) {
            int nb = kt + 2 - 3 * ((kt + 2) / 3);
            load_stage(smb + (uint32_t)nb * STAGE_B, a, b, kt + 2, K, tid);
            asm volatile("cp.async.commit_group;" ::: "memory");
        }

        const uint32_t sA = smb + (uint32_t)buf * STAGE_B;
        const uint32_t sB = sA + A_TILE_B;

        #pragma unroll
        for (int kc = 0; kc < 4; kc++) {
            uint32_t fa[4][4];
            #pragma unroll
            for (int mf = 0; mf < 4; mf++) {
                int row = aRowBase + mf * 16;
                uint32_t kb = (uint32_t)kc * 32 + aKsel;
                uint32_t off = ((uint32_t)row << 7) + (kb ^ (((uint32_t)row & 7u) << 4));
                ldsm_x4(fa[mf], sA + off);
            }
            #pragma unroll
            for (int ng = 0; ng < 4; ng++) {
                uint32_t fb[4];
                int row = bRowBase + ng * 16;
                uint32_t kb = (uint32_t)kc * 32 + bKsel;
                uint32_t off = ((uint32_t)row << 7) + (kb ^ (((uint32_t)row & 7u) << 4));
                ldsm_x4(fb, sB + off);
                #pragma unroll
                for (int mf = 0; mf < 4; mf++) {
                    mma16816(acc[mf][ng * 2 + 0], fa[mf], fb[0], fb[1]);
                    mma16816(acc[mf][ng * 2 + 1], fa[mf], fb[2], fb[3]);
                }
            }
        }
        buf++;
        if (buf == 3) buf = 0;
        __syncthreads();
    }

    // ---- store C ----
    const int r0 = bm * 128 + wm * 64 + (lane >> 2);
    const int c0 = bn * 128 + wn * 64 + (lane & 3) * 2;
    #pragma unroll
    for (int mf = 0; mf < 4; mf++) {
        #pragma unroll
        for (int nf = 0; nf < 8; nf++) {
            OutT* p0 = C + (size_t)(r0 + mf * 16) * N + c0 + nf * 8;
            OutT* p1 = C + (size_t)(r0 + mf * 16 + 8) * N + c0 + nf * 8;
            store_pair<OutT>(p0, acc[mf][nf][0], acc[mf][nf][1]);
            store_pair<OutT>(p1, acc[mf][nf][2], acc[mf][nf][3]);
        }
    }

    // ---- fused column stats over this CTA's 128 rows (fp32 accumulators) ----
    float se[8], so[8], qe[8], qo[8];
    #pragma unroll
    for (int nf = 0; nf < 8; nf++) {
        float s0 = 0.f, s1 = 0.f, q0 = 0.f, q1 = 0.f;
        #pragma unroll
        for (int mf = 0; mf < 4; mf++) {
            float a0 = acc[mf][nf][0], a1 = acc[mf][nf][1];
            float a2 = acc[mf][nf][2], a3 = acc[mf][nf][3];
            s0 += a0 + a2;  s1 += a1 + a3;
            q0 = fmaf(a0, a0, fmaf(a2, a2, q0));
            q1 = fmaf(a1, a1, fmaf(a3, a3, q1));
        }
        se[nf] = s0; so[nf] = s1; qe[nf] = q0; qo[nf] = q1;
    }
    #pragma unroll
    for (int off = 4; off <= 16; off <<= 1) {
        #pragma unroll
        for (int nf = 0; nf < 8; nf++) {
            se[nf] += __shfl_xor_sync(0xffffffffu, se[nf], off);
            so[nf] += __shfl_xor_sync(0xffffffffu, so[nf], off);
            qe[nf] += __shfl_xor_sync(0xffffffffu, qe[nf], off);
            qo[nf] += __shfl_xor_sync(0xffffffffu, qo[nf], off);
        }
    }
    float* ss = (float*)smraw;           // [2][128]
    float* sq = ss + 256;                // [2][128]
    if ((lane >> 2) == 0) {
        #pragma unroll
        for (int nf = 0; nf < 8; nf++) {
            int col = wn * 64 + nf * 8 + (lane & 3) * 2;
            ss[wm * 128 + col]     = se[nf];
            ss[wm * 128 + col + 1] = so[nf];
            sq[wm * 128 + col]     = qe[nf];
            sq[wm * 128 + col + 1] = qo[nf];
        }
    }
    __syncthreads();
    if (tid < 128) {
        g_PS[(size_t)bm * N + bn * 128 + tid] = ss[tid] + ss[128 + tid];
        g_PQ[(size_t)bm * N + bn * 128 + tid] = sq[tid] + sq[128 + tid];
    }
}

// ---------------------------------------------------------------------------
// BN finalize: reduce NSLAB partials -> per-column scale/shift
// ---------------------------------------------------------------------------
__global__ void __launch_bounds__(256) bn_finalize_kernel(
    const float* __restrict__ g, const float* __restrict__ be, int D)
{
    int col = blockIdx.x * 256 + threadIdx.x;
    if (col >= D) return;
    float s = 0.0f, q = 0.0f;
    #pragma unroll 8
    for (int c = 0; c < NSLAB; c++) { s += g_PS[c * D + col]; q += g_PQ[c * D + col]; }
    float invB = 1.0f / (float)BATCH;
    float mean = s * invB;
    float var  = q * invB - mean * mean;
    float sc   = g[col] / sqrtf(var + BN_EPS);
    g_SCALE[col] = sc;
    g_SHIFT[col] = be[col] - mean * sc;
}

// BN+ReLU: fp32 Z -> fp16 activations, 8 outputs/thread
__global__ void __launch_bounds__(256) bn_relu_half_kernel(
    const float* __restrict__ Z, __half* __restrict__ Ao, int D, int total8)
{
    int i = blockIdx.x * 256 + threadIdx.x;
    if (i >= total8) return;
    int col = (i * 8) % D;
    float4 v0 = ((const float4*)Z)[i * 2 + 0];
    float4 v1 = ((const float4*)Z)[i * 2 + 1];
    float4 sc0 = *(const float4*)&g_SCALE[col];
    float4 sc1 = *(const float4*)&g_SCALE[col + 4];
    float4 sh0 = *(const float4*)&g_SHIFT[col];
    float4 sh1 = *(const float4*)&g_SHIFT[col + 4];
    __half2 o[4];
    o[0] = __floats2half2_rn(fmaxf(0.f, fmaf(v0.x, sc0.x, sh0.x)),
                             fmaxf(0.f, fmaf(v0.y, sc0.y, sh0.y)));
    o[1] = __floats2half2_rn(fmaxf(0.f, fmaf(v0.z, sc0.z, sh0.z)),
                             fmaxf(0.f, fmaf(v0.w, sc0.w, sh0.w)));
    o[2] = __floats2half2_rn(fmaxf(0.f, fmaf(v1.x, sc1.x, sh1.x)),
                             fmaxf(0.f, fmaf(v1.y, sc1.y, sh1.y)));
    o[3] = __floats2half2_rn(fmaxf(0.f, fmaf(v1.z, sc1.z, sh1.z)),
                             fmaxf(0.f, fmaf(v1.w, sc1.w, sh1.w)));
    ((uint4*)Ao)[i] = *(uint4*)o;
}

// ---------------------------------------------------------------------------
// Fused BN+ReLU+GEMV head over fp16 raw preacts Z2:
//   out[b] = sum_k relu(Z2[b,k]*sc[k]+sh[k]) * Wout[k] + bout
// ---------------------------------------------------------------------------
__global__ void __launch_bounds__(256) out_bn_gemv_kernel(
    const __half* __restrict__ Z2, const float* __restrict__ Wout,
    const float* __restrict__ bout, float* __restrict__ out)
{
    __shared__ float w[D3], sc[D3], sh[D3];
    int tid = threadIdx.x;
    ((float4*)w)[tid]  = ((const float4*)Wout)[tid];
    ((float4*)sc)[tid] = ((const float4*)g_SCALE)[tid];
    ((float4*)sh)[tid] = ((const float4*)g_SHIFT)[tid];
    __syncthreads();
    int warp = tid >> 5, lane = tid & 31;
    int b = blockIdx.x * 8 + warp;
    const __half* a = Z2 + (size_t)b * D3;
    float sum = 0.0f;
    #pragma unroll
    for (int it = 0; it < 4; it++) {
        int k = it * 256 + lane * 8;
        uint4 zv = *(const uint4*)(a + k);
        const __half2* h = (const __half2*)&zv;
        #pragma unroll
        for (int j = 0; j < 4; j++) {
            float2 f = __half22float2(h[j]);
            int kk = k + j * 2;
            float y0 = fmaxf(0.0f, fmaf(f.x, sc[kk + 0], sh[kk + 0]));
            float y1 = fmaxf(0.0f, fmaf(f.y, sc[kk + 1], sh[kk + 1]));
            sum = fmaf(y0, w[kk + 0], sum);
            sum = fmaf(y1, w[kk + 1], sum);
        }
    }
    #pragma unroll
    for (int off = 16; off > 0; off >>= 1) sum += __shfl_down_sync(0xFFFFFFFFu, sum, off);
    if (lane == 0) out[b] = sum + bout[0];
}

// ---------------------------------------------------------------------------
// Host launcher. Inputs: 0 xv, 1 W0, 2 b0, 3 g0, 4 be0, 5 W1, 6 b1, 7 g1,
// 8 be1, 9 W2, 10 b2, 11 g2, 12 be2, 13 Wout, 14 bout.
// b0/b1/b2 are absorbed by train-mode BatchNorm and never read.
// ---------------------------------------------------------------------------
extern "C" void kernel_launch(void* const* d_in, const int* in_sizes, int n_in,
                              void* d_out, int out_size)
{
    const float* xv   = (const float*)d_in[0];
    const float* W0   = (const float*)d_in[1];
    const float* g0   = (const float*)d_in[3];
    const float* be0  = (const float*)d_in[4];
    const float* W1   = (const float*)d_in[5];
    const float* g1   = (const float*)d_in[7];
    const float* be1  = (const float*)d_in[8];
    const float* W2   = (const float*)d_in[9];
    const float* g2   = (const float*)d_in[11];
    const float* be2  = (const float*)d_in[12];
    const float* Wout = (const float*)d_in[13];
    const float* bout = (const float*)d_in[14];
    float* out = (float*)d_out;

    cudaFuncSetAttribute(gemm_f16_kernel<float>,  cudaFuncAttributeMaxDynamicSharedMemorySize, GEMM_SMEM);
    cudaFuncSetAttribute(gemm_f16_kernel<__half>, cudaFuncAttributeMaxDynamicSharedMemorySize, GEMM_SMEM);

    __half *H0, *Ap, *Z2, *W0h, *W1h, *W2h;
    float *Z;
    cudaGetSymbolAddress((void**)&H0,  g_H0);
    cudaGetSymbolAddress((void**)&Ap,  g_A);
    cudaGetSymbolAddress((void**)&Z,   g_Z);
    cudaGetSymbolAddress((void**)&Z2,  g_Z2);
    cudaGetSymbolAddress((void**)&W0h, g_W0);
    cudaGetSymbolAddress((void**)&W1h, g_W1);
    cudaGetSymbolAddress((void**)&W2h, g_W2);

    // frontend + weight prep
    build_pairs_kernel<<<8, 256>>>();
    build_h0_kernel<<<BATCH, 256>>>(xv);
    convert_w_kernel<<<(int)(((size_t)D1 * K0P / 8 + 255) / 256), 256>>>(W0, W0h, D1, K0, K0P);
    convert_w_kernel<<<(int)(((size_t)D2 * D1 / 8 + 255) / 256), 256>>>(W1, W1h, D2, D1, D1);
    convert_w_kernel<<<(int)(((size_t)D3 * D2 / 8 + 255) / 256), 256>>>(W2, W2h, D3, D2, D2);

    // layer 0: Z = H0 @ W0^T (fp32, stats fused) -> BN+ReLU -> fp16 A
    gemm_f16_kernel<float><<<dim3(D1 / 128, BATCH / 128), 128, GEMM_SMEM>>>(H0, W0h, Z, BATCH, D1, K0P);
    bn_finalize_kernel<<<D1 / 256, 256>>>(g0, be0, D1);
    bn_relu_half_kernel<<<(BATCH * D1 / 8) / 256, 256>>>(Z, Ap, D1, BATCH * D1 / 8);

    // layer 1: Z = A @ W1^T (fp32, stats fused) -> BN+ReLU -> fp16 A
    gemm_f16_kernel<float><<<dim3(D2 / 128, BATCH / 128), 128, GEMM_SMEM>>>(Ap, W1h, Z, BATCH, D2, D1);
    bn_finalize_kernel<<<D2 / 256, 256>>>(g1, be1, D2);
    bn_relu_half_kernel<<<(BATCH * D2 / 8) / 256, 256>>>(Z, Ap, D2, BATCH * D2 / 8);

    // layer 2: Z2 = A @ W2^T (fp16 out, stats fused) — BN folded into the head
    gemm_f16_kernel<__half><<<dim3(D3 / 128, BATCH / 128), 128, GEMM_SMEM>>>(Ap, W2h, Z2, BATCH, D3, D2);
    bn_finalize_kernel<<<D3 / 256, 256>>>(g2, be2, D3);

    // fused BN2+ReLU+GEMV head
    out_bn_gemv_kernel<<<BATCH / 8, 256>>>(Z2, Wout, bout, out);
}